// round 14
// baseline (speedup 1.0000x reference)
#include <cuda_runtime.h>
#include <cuda_fp16.h>
#include <math.h>

#define NN 100000
#define NE 3200000
#define NG 256
#define NB 391             // ceil(NN/256)
#define GB 391             // gemm1 blocks in fused kernel
#define FULL 0xffffffffu

// -------- scratch --------
__device__ __align__(128) __half g_u1h[NN * 32];   // (x@W1)*dinv, fp16 (64B rows — keep 128-aligned!)
__device__ __align__(128) __half g_u2h[NN * 24];   // (h1@W2)*dinv, fp16
__device__ __align__(128) __half g_h2h[NN * 24];   // h2, fp16
__device__ __align__(16) float  g_nlog[NN];        // exp(node logit)
__device__ float    g_dinv[NN];
__device__ int      g_cnti[NN];      // self-cleaned in k_offsets
__device__ int      g_off [NN + 1];
__device__ int      g_cur [NN];
__device__ __align__(16) int g_srt [NE];
__device__ int      g_bsum[NB];
__device__ int      g_done;          // nbf completion counter (reset in k_blocksum)
__device__ __align__(16) float g_gsum_h2[NG * 24];
__device__ __align__(16) float g_bfeat  [NG * 24];
__device__ float    g_cnt  [NG];
__device__ float    g_gsumn[NG];

// ---------------- helpers ----------------
__device__ __forceinline__ float bfly24(float v) {
#pragma unroll
    for (int d = 16; d >= 1; d >>= 1) v += __shfl_xor_sync(FULL, v, d);
    return v;
}
__device__ __forceinline__ void acc8(float* a, uint4 u) {
    const __half2* hp = (const __half2*)&u;
#pragma unroll
    for (int p = 0; p < 4; p++) {
        float2 f = __half22float2(hp[p]);
        a[p*2+0] += f.x; a[p*2+1] += f.y;
    }
}

// ---------------- kernels ----------------

// in-degree histogram, 2 edges/thread (edge_index is int32 — JAX x64 disabled)
__global__ void k_hist(const int* __restrict__ cols, int E) {
    int e = (blockIdx.x * blockDim.x + threadIdx.x) * 2;
    if (e + 1 < E) {
        int2 c = *(const int2*)(cols + e);
        if ((unsigned)c.x < NN) atomicAdd(&g_cnti[c.x], 1);
        if ((unsigned)c.y < NN) atomicAdd(&g_cnti[c.y], 1);
    } else if (e < E) {
        unsigned c = (unsigned)cols[e];
        if (c < NN) atomicAdd(&g_cnti[c], 1);
    }
}

// per-256-block sums of histogram + dinv; block 0 zeroes per-graph scratch + done counter
__global__ __launch_bounds__(256) void k_blocksum() {
    if (blockIdx.x == 0) {
        for (int q = threadIdx.x; q < NG * 24; q += 256) { g_gsum_h2[q] = 0.0f; g_bfeat[q] = 0.0f; }
        if (threadIdx.x < NG) { g_cnt[threadIdx.x] = 0.0f; g_gsumn[threadIdx.x] = 0.0f; }
        if (threadIdx.x == 0) g_done = 0;
    }
    __shared__ int s[256];
    int i = blockIdx.x * 256 + threadIdx.x;
    int v = (i < NN) ? g_cnti[i] : 0;
    if (i < NN) g_dinv[i] = rsqrtf((float)(v + 1));
    s[threadIdx.x] = v;
    __syncthreads();
#pragma unroll
    for (int d = 128; d >= 32; d >>= 1) {
        if (threadIdx.x < d) s[threadIdx.x] += s[threadIdx.x + d];
        __syncthreads();
    }
    if (threadIdx.x < 32) {
        int w = s[threadIdx.x];
#pragma unroll
        for (int d = 16; d >= 1; d >>= 1) w += __shfl_xor_sync(FULL, w, d);
        if (threadIdx.x == 0) g_bsum[blockIdx.x] = w;
    }
}

// offsets: each block computes its own prefix over g_bsum, then local exclusive scan;
// also cursors + cnti self-clean
__global__ __launch_bounds__(256) void k_offsets(int E) {
    __shared__ int s[256];
    __shared__ int s_pre;
    int t = threadIdx.x;
    int blk = blockIdx.x;
    int v1 = (t < blk) ? g_bsum[t] : 0;
    if (t + 256 < blk) v1 += g_bsum[t + 256];
    s[t] = v1;
    __syncthreads();
#pragma unroll
    for (int d = 128; d >= 1; d >>= 1) {
        if (t < d) s[t] += s[t + d];
        __syncthreads();
    }
    if (t == 0) s_pre = s[0];
    __syncthreads();
    int i = blk * 256 + t;
    int v = (i < NN) ? g_cnti[i] : 0;
    s[t] = v;
    __syncthreads();
#pragma unroll
    for (int d = 1; d < 256; d <<= 1) {
        int x = (t >= d) ? s[t - d] : 0;
        __syncthreads();
        s[t] += x;
        __syncthreads();
    }
    if (i < NN) {
        int o = s_pre + s[t] - v;
        g_off[i] = o;
        g_cur[i] = o;
        g_cnti[i] = 0;                        // self-clean for graph replay
    }
    if (i == NN - 1) g_off[NN] = E;
}

// FUSED dual-role kernel — PLACE blocks first (L2-bound, saturates immediately),
// gemm blocks [nPlace, nPlace+GB) trickle in and overlap place's tail.
__global__ __launch_bounds__(256) void k_gemm1place(const float* __restrict__ x,
                                                    const float* __restrict__ W1,
                                                    const int* __restrict__ rows,
                                                    const int* __restrict__ cols,
                                                    int E, int n, int nPlace) {
    __shared__ float4 Ws[32 * 8];
    if (blockIdx.x < nPlace) {
        int e = (blockIdx.x * 256 + threadIdx.x) * 2;
        if (e + 1 < E) {
            int2 r = *(const int2*)(rows + e);
            int2 c = *(const int2*)(cols + e);
            if ((unsigned)c.x < NN && (unsigned)r.x < NN) g_srt[atomicAdd(&g_cur[c.x], 1)] = r.x;
            if ((unsigned)c.y < NN && (unsigned)r.y < NN) g_srt[atomicAdd(&g_cur[c.y], 1)] = r.y;
        } else if (e < E) {
            unsigned c = (unsigned)cols[e], r = (unsigned)rows[e];
            if (c < NN && r < NN) g_srt[atomicAdd(&g_cur[c], 1)] = (int)r;
        }
        return;
    }
    // ---- gemm1 role ----
    for (int t = threadIdx.x; t < 256; t += 256) Ws[t] = ((const float4*)W1)[t];
    __syncthreads();
    int i = (blockIdx.x - nPlace) * 256 + threadIdx.x;
    if (i >= n) return;
    float a[32];
#pragma unroll
    for (int j = 0; j < 32; j++) a[j] = 0.0f;
    const float4* xr = (const float4*)(x + (size_t)i * 32);
#pragma unroll
    for (int k4 = 0; k4 < 8; k4++) {
        float4 xv = xr[k4];
        float xs[4] = {xv.x, xv.y, xv.z, xv.w};
#pragma unroll
        for (int c = 0; c < 4; c++) {
            float v = xs[c];
            int k = k4 * 4 + c;
#pragma unroll
            for (int j4 = 0; j4 < 8; j4++) {
                float4 w = Ws[k * 8 + j4];
                a[j4*4+0] = fmaf(v, w.x, a[j4*4+0]);
                a[j4*4+1] = fmaf(v, w.y, a[j4*4+1]);
                a[j4*4+2] = fmaf(v, w.z, a[j4*4+2]);
                a[j4*4+3] = fmaf(v, w.w, a[j4*4+3]);
            }
        }
    }
    float di = g_dinv[i];
    __half2 hp[16];
#pragma unroll
    for (int p = 0; p < 16; p++) hp[p] = __floats2half2_rn(a[p*2] * di, a[p*2+1] * di);
    uint4* out = (uint4*)g_u1h + (size_t)i * 4;
    const uint4* src = (const uint4*)hp;
#pragma unroll
    for (int q = 0; q < 4; q++) out[q] = src[q];
}

// fused: aggregate conv1 (4 thr/node, fp16 gather, int4 index loads) + relu/bias + GEMM W2.
__global__ __launch_bounds__(128) void k_aggrfin1(const float* __restrict__ b1,
                                                  const float* __restrict__ W2, int n) {
    __shared__ float Ws[32 * 24];
    __shared__ float bs[32];
    __shared__ float hs[32][33];
    for (int t = threadIdx.x; t < 768; t += 128) Ws[t] = W2[t];
    if (threadIdx.x < 32) bs[threadIdx.x] = b1[threadIdx.x];
    __syncthreads();                   // guard Ws/bs
    int local = threadIdx.x >> 2;
    int sub   = threadIdx.x & 3;       // 8 feats each (16B)
    int node  = blockIdx.x * 32 + local;
    bool valid = node < n;
    float acc[8];
#pragma unroll
    for (int f = 0; f < 8; f++) acc[f] = 0.0f;
    float di = 0.0f;
    if (valid) {
        const uint4* U = (const uint4*)g_u1h;
        acc8(acc, U[(size_t)node * 4 + sub]);     // self loop
        int s = g_off[node], e = g_off[node + 1];
        int j = s;
        for (; j < e && (j & 3); j++) acc8(acc, U[(size_t)g_srt[j] * 4 + sub]);
        for (; j + 4 <= e; j += 4) {
            int4 rr = *(const int4*)(g_srt + j);
            uint4 v0 = U[(size_t)rr.x * 4 + sub];
            uint4 v1 = U[(size_t)rr.y * 4 + sub];
            uint4 v2 = U[(size_t)rr.z * 4 + sub];
            uint4 v3 = U[(size_t)rr.w * 4 + sub];
            acc8(acc, v0); acc8(acc, v1); acc8(acc, v2); acc8(acc, v3);
        }
        for (; j < e; j++) acc8(acc, U[(size_t)g_srt[j] * 4 + sub]);
        di = g_dinv[node];
#pragma unroll
        for (int f = 0; f < 8; f++)
            hs[local][sub * 8 + f] = fmaxf(di * acc[f] + bs[sub * 8 + f], 0.0f);
    }
    __syncwarp();                      // warp-local handoff (4 | 32)
    if (!valid) return;
    float a[6];
#pragma unroll
    for (int q = 0; q < 6; q++) a[q] = 0.0f;
#pragma unroll
    for (int k = 0; k < 32; k++) {
        float v = hs[local][k];
        const float* wr = &Ws[k * 24 + sub * 6];
#pragma unroll
        for (int q = 0; q < 6; q++) a[q] = fmaf(v, wr[q], a[q]);
    }
    __half2* out = (__half2*)(g_u2h + (size_t)node * 24 + sub * 6);
#pragma unroll
    for (int q = 0; q < 3; q++)
        out[q] = __floats2half2_rn(a[q*2] * di, a[q*2+1] * di);
}

// fused: aggregate conv2 (3 thr/node, int4 index loads) + h2 fp16 + node MLP + exp + per-graph sums
__global__ __launch_bounds__(192) void k_aggrfin2(const float* __restrict__ b2,
                                                  const float* __restrict__ Wn1, const float* __restrict__ bn1,
                                                  const float* __restrict__ Wn2, const float* __restrict__ bn2,
                                                  const int* __restrict__ batch, int n) {
    __shared__ float W1s[24 * 16];
    __shared__ float b1s[16];
    __shared__ float W2s[16];
    __shared__ float b2s[24];
    __shared__ float hs[64][25];
    for (int t = threadIdx.x; t < 384; t += 192) W1s[t] = Wn1[t];
    if (threadIdx.x < 16) { b1s[threadIdx.x] = bn1[threadIdx.x]; W2s[threadIdx.x] = Wn2[threadIdx.x]; }
    if (threadIdx.x < 24) b2s[threadIdx.x] = b2[threadIdx.x];
    int local = threadIdx.x / 3;
    int sub   = threadIdx.x % 3;       // 8 feats each (16B)
    int node  = blockIdx.x * 64 + local;
    bool valid = (node < n) && (local < 64);
    float acc[8];
#pragma unroll
    for (int f = 0; f < 8; f++) acc[f] = 0.0f;
    if (valid) {
        const uint4* U = (const uint4*)g_u2h;
        acc8(acc, U[(size_t)node * 3 + sub]);     // self loop
        int s = g_off[node], e = g_off[node + 1];
        int j = s;
        for (; j < e && (j & 3); j++) acc8(acc, U[(size_t)g_srt[j] * 3 + sub]);
        for (; j + 4 <= e; j += 4) {
            int4 rr = *(const int4*)(g_srt + j);
            uint4 v0 = U[(size_t)rr.x * 3 + sub];
            uint4 v1 = U[(size_t)rr.y * 3 + sub];
            uint4 v2 = U[(size_t)rr.z * 3 + sub];
            uint4 v3 = U[(size_t)rr.w * 3 + sub];
            acc8(acc, v0); acc8(acc, v1); acc8(acc, v2); acc8(acc, v3);
        }
        for (; j < e; j++) acc8(acc, U[(size_t)g_srt[j] * 3 + sub]);
        float di = g_dinv[node];
        __half2 hp[4];
#pragma unroll
        for (int p = 0; p < 4; p++) {
            float h0 = fmaxf(di * acc[p*2+0] + b2s[sub*8 + p*2+0], 0.0f);
            float h1 = fmaxf(di * acc[p*2+1] + b2s[sub*8 + p*2+1], 0.0f);
            hs[local][sub*8 + p*2+0] = h0;
            hs[local][sub*8 + p*2+1] = h1;
            hp[p] = __floats2half2_rn(h0, h1);
        }
        ((uint4*)g_h2h)[(size_t)node * 3 + sub] = *(const uint4*)hp;
    }
    __syncthreads();
    // phase 3: warps 0,1 — one node per lane
    if (threadIdx.x >= 64) return;
    int tid = threadIdx.x;
    int node2 = blockIdx.x * 64 + tid;
    bool v2 = node2 < n;
    float h[24];
    float ex = 0.0f;
    unsigned b = 0xffffffffu;
    if (v2) {
#pragma unroll
        for (int k = 0; k < 24; k++) h[k] = hs[tid][k];
        float m[16];
#pragma unroll
        for (int o = 0; o < 16; o++) m[o] = b1s[o];
#pragma unroll
        for (int k = 0; k < 24; k++) {
            float v = h[k];
            const float* wr = &W1s[k * 16];
#pragma unroll
            for (int o = 0; o < 16; o++) m[o] = fmaf(v, wr[o], m[o]);
        }
        float nl = bn2[0];
#pragma unroll
        for (int o = 0; o < 16; o++) nl = fmaf(fmaxf(m[o], 0.0f), W2s[o], nl);
        ex = __expf(nl);
        g_nlog[node2] = ex;
        b = (unsigned)batch[node2];
    } else {
#pragma unroll
        for (int k = 0; k < 24; k++) h[k] = 0.0f;
    }
    unsigned mask = __match_any_sync(FULL, b);
    int lane = tid & 31;
    if (mask == FULL && v2) {
        float se = bfly24(ex);
#pragma unroll
        for (int j = 0; j < 24; j++) {
            float v = bfly24(h[j]);
            if (lane == j) atomicAdd(&g_gsum_h2[b * 24 + j], v);
        }
        if (lane == 24) atomicAdd(&g_cnt[b], 32.0f);
        if (lane == 25) atomicAdd(&g_gsumn[b], se);
    } else if (v2 && b < NG) {
        atomicAdd(&g_cnt[b], 1.0f);
        atomicAdd(&g_gsumn[b], ex);
#pragma unroll
        for (int j = 0; j < 24; j++) atomicAdd(&g_gsum_h2[b * 24 + j], h[j]);
    }
}

// n = e/gsum; out_n; bfeat += n*h2; LAST block also computes the per-graph heads (fused k_heads)
__global__ __launch_bounds__(256) void k_nbf_heads(const int* __restrict__ batch,
                                                   float* __restrict__ out_n, int n,
                                                   const float* __restrict__ Wg, const float* __restrict__ bg,
                                                   const float* __restrict__ Wt, const float* __restrict__ bt,
                                                   const float* __restrict__ Wb1, const float* __restrict__ bb1,
                                                   const float* __restrict__ Wb2, const float* __restrict__ bb2,
                                                   float* __restrict__ out_t, float* __restrict__ out_bb) {
    int i = blockIdx.x * blockDim.x + threadIdx.x;
    bool valid = i < n;
    unsigned b = 0xffffffffu;
    float val = 0.0f;
    float h[24];
    if (valid) {
        b = (unsigned)batch[i];
        val = g_nlog[i] / g_gsumn[b];
        out_n[i] = val;
        const uint4* hr = (const uint4*)(g_h2h + (size_t)i * 24);
#pragma unroll
        for (int k = 0; k < 3; k++) {
            uint4 u = hr[k];
            const __half2* hp = (const __half2*)&u;
#pragma unroll
            for (int p = 0; p < 4; p++) {
                float2 f = __half22float2(hp[p]);
                h[k*8 + p*2+0] = f.x; h[k*8 + p*2+1] = f.y;
            }
        }
    } else {
#pragma unroll
        for (int j = 0; j < 24; j++) h[j] = 0.0f;
    }
    unsigned mask = __match_any_sync(FULL, b);
    int lane = threadIdx.x & 31;
    if (mask == FULL && valid) {
#pragma unroll
        for (int j = 0; j < 24; j++) {
            float v = bfly24(val * h[j]);
            if (lane == j) atomicAdd(&g_bfeat[b * 24 + j], v);
        }
    } else if (valid && b < NG) {
#pragma unroll
        for (int j = 0; j < 24; j++) atomicAdd(&g_bfeat[b * 24 + j], val * h[j]);
    }

    // -------- last-block heads epilogue --------
    __shared__ int s_last;
    __threadfence();
    __syncthreads();
    if (threadIdx.x == 0) s_last = (atomicAdd(&g_done, 1) == gridDim.x - 1) ? 1 : 0;
    __syncthreads();
    if (!s_last) return;

    __shared__ float sBB[NG * 3];
    __shared__ float cmax[3], csum[3];
    int bb = threadIdx.x;              // NG == blockDim == 256

    float c = fmaxf(g_cnt[bb], 1.0f);
    float g24[24];
#pragma unroll
    for (int j = 0; j < 24; j++) g24[j] = g_gsum_h2[bb * 24 + j] / c;
    float t0 = bt[0], t1 = bt[1];
    for (int o = 0; o < 32; o++) {
        float go = bg[o];
#pragma unroll
        for (int k = 0; k < 24; k++) go = fmaf(g24[k], Wg[k * 32 + o], go);
        t0 = fmaf(go, Wt[o * 2 + 0], t0);
        t1 = fmaf(go, Wt[o * 2 + 1], t1);
    }
    float mx = fmaxf(t0, t1);
    float e0 = __expf(t0 - mx), e1 = __expf(t1 - mx);
    float s = e0 + e1;
    out_t[2 * bb + 0] = e0 / s;
    out_t[2 * bb + 1] = e1 / s;

    float bf[24];
#pragma unroll
    for (int k = 0; k < 24; k++) bf[k] = g_bfeat[bb * 24 + k];
    float r16[16];
#pragma unroll
    for (int o = 0; o < 16; o++) {
        float v = bb1[o];
#pragma unroll
        for (int k = 0; k < 24; k++) v = fmaf(bf[k], Wb1[k * 16 + o], v);
        r16[o] = fmaxf(v, 0.0f);
    }
#pragma unroll
    for (int o = 0; o < 3; o++) {
        float v = bb2[o];
#pragma unroll
        for (int k = 0; k < 16; k++) v = fmaf(r16[k], Wb2[k * 3 + o], v);
        sBB[bb * 3 + o] = v;
    }
    __syncthreads();
    if (bb < 3) {
        float m = -3.4e38f;
        for (int r = 0; r < NG; r++) m = fmaxf(m, sBB[r * 3 + bb]);
        float ss = 0.0f;
        for (int r = 0; r < NG; r++) ss += __expf(sBB[r * 3 + bb] - m);
        cmax[bb] = m; csum[bb] = ss;
    }
    __syncthreads();
#pragma unroll
    for (int o = 0; o < 3; o++)
        out_bb[bb * 3 + o] = __expf(sBB[bb * 3 + o] - cmax[o]) / csum[o];
}

// ---------------- launcher ----------------
extern "C" void kernel_launch(void* const* d_in, const int* in_sizes, int n_in,
                              void* d_out, int out_size) {
    const float* x   = (const float*)d_in[0];
    const int*   ei  = (const int*)d_in[1];
    const int*   bat = (const int*)d_in[2];
    const float *W1 = (const float*)d_in[3],  *b1 = (const float*)d_in[4];
    const float *W2 = (const float*)d_in[5];
    const float *b2 = (const float*)d_in[6];
    const float *Wg = (const float*)d_in[7],  *bg = (const float*)d_in[8];
    const float *Wt = (const float*)d_in[9],  *bt = (const float*)d_in[10];
    const float *Wn1= (const float*)d_in[11], *bn1= (const float*)d_in[12];
    const float *Wn2= (const float*)d_in[13], *bn2= (const float*)d_in[14];
    const float *Wb1= (const float*)d_in[15], *bb1= (const float*)d_in[16];
    const float *Wb2= (const float*)d_in[17], *bb2= (const float*)d_in[18];

    const int N = in_sizes[0] / 32;
    const int E = in_sizes[1] / 2;
    const int* rows = ei;       // edge_index[0] = source
    const int* cols = ei + E;   // edge_index[1] = target

    float* out = (float*)d_out;
    float* out_t  = out;              // [256,2]
    float* out_n  = out + NG * 2;     // [N,1]
    float* out_bb = out + NG * 2 + N; // [256,3]

    const int TB = 256;
    const int nPlace = (E / 2 + 255) / 256;
    const int nGemm  = (N + 255) / 256;
    k_hist<<<(E / 2 + TB - 1) / TB, TB>>>(cols, E);
    k_blocksum<<<NB, 256>>>();
    k_offsets<<<NB, 256>>>(E);
    k_gemm1place<<<nPlace + nGemm, 256>>>(x, W1, rows, cols, E, N, nPlace);
    k_aggrfin1<<<(N + 31) / 32, 128>>>(b1, W2, N);
    k_aggrfin2<<<(N + 63) / 64, 192>>>(b2, Wn1, bn1, Wn2, bn2, bat, N);
    k_nbf_heads<<<(N + 255) / 256, 256>>>(bat, out_n, N,
                                          Wg, bg, Wt, bt, Wb1, bb1, Wb2, bb2, out_t, out_bb);
}

// round 15
// speedup vs baseline: 1.0218x; 1.0218x over previous
#include <cuda_runtime.h>
#include <cuda_fp16.h>
#include <math.h>

#define NN 100000
#define NE 3200000
#define NG 256
#define NB 391             // ceil(NN/256)
#define GB 391             // gemm1 role blocks
#define FULL 0xffffffffu

// -------- scratch --------
__device__ __align__(128) __half g_u1h[NN * 32];   // x@W1 (raw, then *dinv in placescale), fp16
__device__ __align__(128) __half g_u2h[NN * 24];   // (h1@W2)*dinv, fp16
__device__ __align__(128) __half g_h2h[NN * 24];   // h2, fp16
__device__ __align__(16) float  g_nlog[NN];        // exp(node logit)
__device__ float    g_dinv[NN];
__device__ int      g_cnti[NN];      // self-cleaned in k_offsets
__device__ int      g_off [NN + 1];
__device__ int      g_cur [NN];
__device__ __align__(16) int g_srt [NE];
__device__ int      g_bsum[NB];
__device__ __align__(16) float g_gsum_h2[NG * 24];
__device__ __align__(16) float g_bfeat  [NG * 24];
__device__ float    g_cnt  [NG];
__device__ float    g_gsumn[NG];

// ---------------- helpers ----------------
__device__ __forceinline__ float bfly24(float v) {
#pragma unroll
    for (int d = 16; d >= 1; d >>= 1) v += __shfl_xor_sync(FULL, v, d);
    return v;
}
__device__ __forceinline__ void acc8(float* a, uint4 u) {
    const __half2* hp = (const __half2*)&u;
#pragma unroll
    for (int p = 0; p < 4; p++) {
        float2 f = __half22float2(hp[p]);
        a[p*2+0] += f.x; a[p*2+1] += f.y;
    }
}

// ---------------- kernels ----------------

// FUSED: blocks [0,GB) = gemm1 (x@W1 -> u1 RAW fp16; no dinv dependency!),
// blocks [GB,...) = in-degree histogram. The two roles are fully independent.
__global__ __launch_bounds__(256) void k_g1h(const float* __restrict__ x,
                                             const float* __restrict__ W1,
                                             const int* __restrict__ cols,
                                             int E, int n) {
    __shared__ float4 Ws[32 * 8];
    if (blockIdx.x >= GB) {
        // ---- hist role ----
        int e = ((blockIdx.x - GB) * 256 + threadIdx.x) * 2;
        if (e + 1 < E) {
            int2 c = *(const int2*)(cols + e);
            if ((unsigned)c.x < NN) atomicAdd(&g_cnti[c.x], 1);
            if ((unsigned)c.y < NN) atomicAdd(&g_cnti[c.y], 1);
        } else if (e < E) {
            unsigned c = (unsigned)cols[e];
            if (c < NN) atomicAdd(&g_cnti[c], 1);
        }
        return;
    }
    // ---- gemm1 role (no dinv) ----
    for (int t = threadIdx.x; t < 256; t += 256) Ws[t] = ((const float4*)W1)[t];
    __syncthreads();
    int i = blockIdx.x * 256 + threadIdx.x;
    if (i >= n) return;
    float a[32];
#pragma unroll
    for (int j = 0; j < 32; j++) a[j] = 0.0f;
    const float4* xr = (const float4*)(x + (size_t)i * 32);
#pragma unroll
    for (int k4 = 0; k4 < 8; k4++) {
        float4 xv = xr[k4];
        float xs[4] = {xv.x, xv.y, xv.z, xv.w};
#pragma unroll
        for (int c = 0; c < 4; c++) {
            float v = xs[c];
            int k = k4 * 4 + c;
#pragma unroll
            for (int j4 = 0; j4 < 8; j4++) {
                float4 w = Ws[k * 8 + j4];
                a[j4*4+0] = fmaf(v, w.x, a[j4*4+0]);
                a[j4*4+1] = fmaf(v, w.y, a[j4*4+1]);
                a[j4*4+2] = fmaf(v, w.z, a[j4*4+2]);
                a[j4*4+3] = fmaf(v, w.w, a[j4*4+3]);
            }
        }
    }
    __half2 hp[16];
#pragma unroll
    for (int p = 0; p < 16; p++) hp[p] = __floats2half2_rn(a[p*2], a[p*2+1]);
    uint4* out = (uint4*)g_u1h + (size_t)i * 4;
    const uint4* src = (const uint4*)hp;
#pragma unroll
    for (int q = 0; q < 4; q++) out[q] = src[q];
}

// per-256-block sums of histogram + dinv; block 0 zeroes per-graph scratch
__global__ __launch_bounds__(256) void k_blocksum() {
    if (blockIdx.x == 0) {
        for (int q = threadIdx.x; q < NG * 24; q += 256) { g_gsum_h2[q] = 0.0f; g_bfeat[q] = 0.0f; }
        if (threadIdx.x < NG) { g_cnt[threadIdx.x] = 0.0f; g_gsumn[threadIdx.x] = 0.0f; }
    }
    __shared__ int s[256];
    int i = blockIdx.x * 256 + threadIdx.x;
    int v = (i < NN) ? g_cnti[i] : 0;
    if (i < NN) g_dinv[i] = rsqrtf((float)(v + 1));
    s[threadIdx.x] = v;
    __syncthreads();
#pragma unroll
    for (int d = 128; d >= 32; d >>= 1) {
        if (threadIdx.x < d) s[threadIdx.x] += s[threadIdx.x + d];
        __syncthreads();
    }
    if (threadIdx.x < 32) {
        int w = s[threadIdx.x];
#pragma unroll
        for (int d = 16; d >= 1; d >>= 1) w += __shfl_xor_sync(FULL, w, d);
        if (threadIdx.x == 0) g_bsum[blockIdx.x] = w;
    }
}

// offsets: each block computes its own prefix over g_bsum, then local exclusive scan;
// also cursors + cnti self-clean
__global__ __launch_bounds__(256) void k_offsets(int E) {
    __shared__ int s[256];
    __shared__ int s_pre;
    int t = threadIdx.x;
    int blk = blockIdx.x;
    int v1 = (t < blk) ? g_bsum[t] : 0;
    if (t + 256 < blk) v1 += g_bsum[t + 256];
    s[t] = v1;
    __syncthreads();
#pragma unroll
    for (int d = 128; d >= 1; d >>= 1) {
        if (t < d) s[t] += s[t + d];
        __syncthreads();
    }
    if (t == 0) s_pre = s[0];
    __syncthreads();
    int i = blk * 256 + t;
    int v = (i < NN) ? g_cnti[i] : 0;
    s[t] = v;
    __syncthreads();
#pragma unroll
    for (int d = 1; d < 256; d <<= 1) {
        int x = (t >= d) ? s[t - d] : 0;
        __syncthreads();
        s[t] += x;
        __syncthreads();
    }
    if (i < NN) {
        int o = s_pre + s[t] - v;
        g_off[i] = o;
        g_cur[i] = o;
        g_cnti[i] = 0;                        // self-clean for graph replay
    }
    if (i == NN - 1) g_off[NN] = E;
}

// FUSED: blocks [0,nScale) scale u1h by dinv (coalesced), blocks [nScale,...) do CSR placement
__global__ __launch_bounds__(256) void k_placescale(const int* __restrict__ rows,
                                                    const int* __restrict__ cols,
                                                    int E, int n, int nScale) {
    if (blockIdx.x >= nScale) {
        // ---- place role ----
        int e = ((blockIdx.x - nScale) * 256 + threadIdx.x) * 2;
        if (e + 1 < E) {
            int2 r = *(const int2*)(rows + e);
            int2 c = *(const int2*)(cols + e);
            if ((unsigned)c.x < NN && (unsigned)r.x < NN) g_srt[atomicAdd(&g_cur[c.x], 1)] = r.x;
            if ((unsigned)c.y < NN && (unsigned)r.y < NN) g_srt[atomicAdd(&g_cur[c.y], 1)] = r.y;
        } else if (e < E) {
            unsigned c = (unsigned)cols[e], r = (unsigned)rows[e];
            if (c < NN && r < NN) g_srt[atomicAdd(&g_cur[c], 1)] = (int)r;
        }
        return;
    }
    // ---- scale role: u1h[idx] *= dinv[node], one uint4 (8 halves) per thread ----
    int idx = blockIdx.x * 256 + threadIdx.x;
    if (idx >= n * 8) return;
    int node = idx >> 3;
    float di = g_dinv[node];
    uint4 u = ((const uint4*)g_u1h)[idx];
    __half2* hp = (__half2*)&u;
#pragma unroll
    for (int p = 0; p < 4; p++) {
        float2 f = __half22float2(hp[p]);
        hp[p] = __floats2half2_rn(f.x * di, f.y * di);
    }
    ((uint4*)g_u1h)[idx] = u;
}

// fused: aggregate conv1 (4 thr/node, fp16 gather, int4 index loads) + relu/bias + GEMM W2
__global__ __launch_bounds__(128) void k_aggrfin1(const float* __restrict__ b1,
                                                  const float* __restrict__ W2, int n) {
    __shared__ float Ws[32 * 24];
    __shared__ float bs[32];
    __shared__ float hs[32][33];
    for (int t = threadIdx.x; t < 768; t += 128) Ws[t] = W2[t];
    if (threadIdx.x < 32) bs[threadIdx.x] = b1[threadIdx.x];
    int local = threadIdx.x >> 2;
    int sub   = threadIdx.x & 3;       // 8 feats each (16B)
    int node  = blockIdx.x * 32 + local;
    bool valid = node < n;
    float acc[8];
#pragma unroll
    for (int f = 0; f < 8; f++) acc[f] = 0.0f;
    float di = 0.0f;
    if (valid) {
        const uint4* U = (const uint4*)g_u1h;
        acc8(acc, U[(size_t)node * 4 + sub]);     // self loop
        int s = g_off[node], e = g_off[node + 1];
        int j = s;
        for (; j < e && (j & 3); j++) acc8(acc, U[(size_t)g_srt[j] * 4 + sub]);
        for (; j + 4 <= e; j += 4) {
            int4 rr = *(const int4*)(g_srt + j);
            uint4 v0 = U[(size_t)rr.x * 4 + sub];
            uint4 v1 = U[(size_t)rr.y * 4 + sub];
            uint4 v2 = U[(size_t)rr.z * 4 + sub];
            uint4 v3 = U[(size_t)rr.w * 4 + sub];
            acc8(acc, v0); acc8(acc, v1); acc8(acc, v2); acc8(acc, v3);
        }
        for (; j < e; j++) acc8(acc, U[(size_t)g_srt[j] * 4 + sub]);
        di = g_dinv[node];
#pragma unroll
        for (int f = 0; f < 8; f++)
            hs[local][sub * 8 + f] = fmaxf(di * acc[f] + bs[sub * 8 + f], 0.0f);
    }
    __syncthreads();
    if (!valid) return;
    float a[6];
#pragma unroll
    for (int q = 0; q < 6; q++) a[q] = 0.0f;
#pragma unroll
    for (int k = 0; k < 32; k++) {
        float v = hs[local][k];
        const float* wr = &Ws[k * 24 + sub * 6];
#pragma unroll
        for (int q = 0; q < 6; q++) a[q] = fmaf(v, wr[q], a[q]);
    }
    __half2* out = (__half2*)(g_u2h + (size_t)node * 24 + sub * 6);
#pragma unroll
    for (int q = 0; q < 3; q++)
        out[q] = __floats2half2_rn(a[q*2] * di, a[q*2+1] * di);
}

// fused: aggregate conv2 (3 thr/node, int4 index loads) + h2 fp16 + node MLP + exp + per-graph sums
__global__ __launch_bounds__(192) void k_aggrfin2(const float* __restrict__ b2,
                                                  const float* __restrict__ Wn1, const float* __restrict__ bn1,
                                                  const float* __restrict__ Wn2, const float* __restrict__ bn2,
                                                  const int* __restrict__ batch, int n) {
    __shared__ float W1s[24 * 16];
    __shared__ float b1s[16];
    __shared__ float W2s[16];
    __shared__ float b2s[24];
    __shared__ float hs[64][25];
    for (int t = threadIdx.x; t < 384; t += 192) W1s[t] = Wn1[t];
    if (threadIdx.x < 16) { b1s[threadIdx.x] = bn1[threadIdx.x]; W2s[threadIdx.x] = Wn2[threadIdx.x]; }
    if (threadIdx.x < 24) b2s[threadIdx.x] = b2[threadIdx.x];
    int local = threadIdx.x / 3;
    int sub   = threadIdx.x % 3;       // 8 feats each (16B)
    int node  = blockIdx.x * 64 + local;
    bool valid = (node < n) && (local < 64);
    float acc[8];
#pragma unroll
    for (int f = 0; f < 8; f++) acc[f] = 0.0f;
    if (valid) {
        const uint4* U = (const uint4*)g_u2h;
        acc8(acc, U[(size_t)node * 3 + sub]);     // self loop
        int s = g_off[node], e = g_off[node + 1];
        int j = s;
        for (; j < e && (j & 3); j++) acc8(acc, U[(size_t)g_srt[j] * 3 + sub]);
        for (; j + 4 <= e; j += 4) {
            int4 rr = *(const int4*)(g_srt + j);
            uint4 v0 = U[(size_t)rr.x * 3 + sub];
            uint4 v1 = U[(size_t)rr.y * 3 + sub];
            uint4 v2 = U[(size_t)rr.z * 3 + sub];
            uint4 v3 = U[(size_t)rr.w * 3 + sub];
            acc8(acc, v0); acc8(acc, v1); acc8(acc, v2); acc8(acc, v3);
        }
        for (; j < e; j++) acc8(acc, U[(size_t)g_srt[j] * 3 + sub]);
        float di = g_dinv[node];
        __half2 hp[4];
#pragma unroll
        for (int p = 0; p < 4; p++) {
            float h0 = fmaxf(di * acc[p*2+0] + b2s[sub*8 + p*2+0], 0.0f);
            float h1 = fmaxf(di * acc[p*2+1] + b2s[sub*8 + p*2+1], 0.0f);
            hs[local][sub*8 + p*2+0] = h0;
            hs[local][sub*8 + p*2+1] = h1;
            hp[p] = __floats2half2_rn(h0, h1);
        }
        ((uint4*)g_h2h)[(size_t)node * 3 + sub] = *(const uint4*)hp;
    }
    __syncthreads();
    // phase 3: warps 0,1 — one node per lane
    if (threadIdx.x >= 64) return;
    int tid = threadIdx.x;
    int node2 = blockIdx.x * 64 + tid;
    bool v2 = node2 < n;
    float h[24];
    float ex = 0.0f;
    unsigned b = 0xffffffffu;
    if (v2) {
#pragma unroll
        for (int k = 0; k < 24; k++) h[k] = hs[tid][k];
        float m[16];
#pragma unroll
        for (int o = 0; o < 16; o++) m[o] = b1s[o];
#pragma unroll
        for (int k = 0; k < 24; k++) {
            float v = h[k];
            const float* wr = &W1s[k * 16];
#pragma unroll
            for (int o = 0; o < 16; o++) m[o] = fmaf(v, wr[o], m[o]);
        }
        float nl = bn2[0];
#pragma unroll
        for (int o = 0; o < 16; o++) nl = fmaf(fmaxf(m[o], 0.0f), W2s[o], nl);
        ex = __expf(nl);
        g_nlog[node2] = ex;
        b = (unsigned)batch[node2];
    } else {
#pragma unroll
        for (int k = 0; k < 24; k++) h[k] = 0.0f;
    }
    unsigned mask = __match_any_sync(FULL, b);
    int lane = tid & 31;
    if (mask == FULL && v2) {
        float se = bfly24(ex);
#pragma unroll
        for (int j = 0; j < 24; j++) {
            float v = bfly24(h[j]);
            if (lane == j) atomicAdd(&g_gsum_h2[b * 24 + j], v);
        }
        if (lane == 24) atomicAdd(&g_cnt[b], 32.0f);
        if (lane == 25) atomicAdd(&g_gsumn[b], se);
    } else if (v2 && b < NG) {
        atomicAdd(&g_cnt[b], 1.0f);
        atomicAdd(&g_gsumn[b], ex);
#pragma unroll
        for (int j = 0; j < 24; j++) atomicAdd(&g_gsum_h2[b * 24 + j], h[j]);
    }
}

// n = e/gsum; write out_n; bfeat[b] += n*h2[i]  (direct coalesced row loads, warp-segmented)
__global__ __launch_bounds__(256) void k_nbf(const int* __restrict__ batch,
                                             float* __restrict__ out_n, int n) {
    int i = blockIdx.x * blockDim.x + threadIdx.x;
    bool valid = i < n;
    unsigned b = 0xffffffffu;
    float val = 0.0f;
    float h[24];
    if (valid) {
        b = (unsigned)batch[i];
        val = g_nlog[i] / g_gsumn[b];
        out_n[i] = val;
        const uint4* hr = (const uint4*)(g_h2h + (size_t)i * 24);
#pragma unroll
        for (int k = 0; k < 3; k++) {
            uint4 u = hr[k];
            const __half2* hp = (const __half2*)&u;
#pragma unroll
            for (int p = 0; p < 4; p++) {
                float2 f = __half22float2(hp[p]);
                h[k*8 + p*2+0] = f.x; h[k*8 + p*2+1] = f.y;
            }
        }
    } else {
#pragma unroll
        for (int j = 0; j < 24; j++) h[j] = 0.0f;
    }
    unsigned mask = __match_any_sync(FULL, b);
    int lane = threadIdx.x & 31;
    if (mask == FULL && valid) {
#pragma unroll
        for (int j = 0; j < 24; j++) {
            float v = bfly24(val * h[j]);
            if (lane == j) atomicAdd(&g_bfeat[b * 24 + j], v);
        }
    } else if (valid && b < NG) {
#pragma unroll
        for (int j = 0; j < 24; j++) atomicAdd(&g_bfeat[b * 24 + j], val * h[j]);
    }
}

// per-graph heads
__global__ __launch_bounds__(256) void k_heads(const float* __restrict__ Wg, const float* __restrict__ bg,
                                               const float* __restrict__ Wt, const float* __restrict__ bt,
                                               const float* __restrict__ Wb1, const float* __restrict__ bb1,
                                               const float* __restrict__ Wb2, const float* __restrict__ bb2,
                                               float* __restrict__ out_t, float* __restrict__ out_bb) {
    __shared__ float sBB[NG * 3];
    __shared__ float cmax[3], csum[3];
    int b = threadIdx.x;

    float c = fmaxf(g_cnt[b], 1.0f);
    float g24[24];
#pragma unroll
    for (int j = 0; j < 24; j++) g24[j] = g_gsum_h2[b * 24 + j] / c;
    float t0 = bt[0], t1 = bt[1];
    for (int o = 0; o < 32; o++) {
        float go = bg[o];
#pragma unroll
        for (int k = 0; k < 24; k++) go = fmaf(g24[k], Wg[k * 32 + o], go);
        t0 = fmaf(go, Wt[o * 2 + 0], t0);
        t1 = fmaf(go, Wt[o * 2 + 1], t1);
    }
    float mx = fmaxf(t0, t1);
    float e0 = __expf(t0 - mx), e1 = __expf(t1 - mx);
    float s = e0 + e1;
    out_t[2 * b + 0] = e0 / s;
    out_t[2 * b + 1] = e1 / s;

    float bf[24];
#pragma unroll
    for (int k = 0; k < 24; k++) bf[k] = g_bfeat[b * 24 + k];
    float r16[16];
#pragma unroll
    for (int o = 0; o < 16; o++) {
        float v = bb1[o];
#pragma unroll
        for (int k = 0; k < 24; k++) v = fmaf(bf[k], Wb1[k * 16 + o], v);
        r16[o] = fmaxf(v, 0.0f);
    }
#pragma unroll
    for (int o = 0; o < 3; o++) {
        float v = bb2[o];
#pragma unroll
        for (int k = 0; k < 16; k++) v = fmaf(r16[k], Wb2[k * 3 + o], v);
        sBB[b * 3 + o] = v;
    }
    __syncthreads();
    if (b < 3) {
        float m = -3.4e38f;
        for (int r = 0; r < NG; r++) m = fmaxf(m, sBB[r * 3 + b]);
        float ss = 0.0f;
        for (int r = 0; r < NG; r++) ss += __expf(sBB[r * 3 + b] - m);
        cmax[b] = m; csum[b] = ss;
    }
    __syncthreads();
#pragma unroll
    for (int o = 0; o < 3; o++)
        out_bb[b * 3 + o] = __expf(sBB[b * 3 + o] - cmax[o]) / csum[o];
}

// ---------------- launcher ----------------
extern "C" void kernel_launch(void* const* d_in, const int* in_sizes, int n_in,
                              void* d_out, int out_size) {
    const float* x   = (const float*)d_in[0];
    const int*   ei  = (const int*)d_in[1];
    const int*   bat = (const int*)d_in[2];
    const float *W1 = (const float*)d_in[3],  *b1 = (const float*)d_in[4];
    const float *W2 = (const float*)d_in[5];
    const float *b2 = (const float*)d_in[6];
    const float *Wg = (const float*)d_in[7],  *bg = (const float*)d_in[8];
    const float *Wt = (const float*)d_in[9],  *bt = (const float*)d_in[10];
    const float *Wn1= (const float*)d_in[11], *bn1= (const float*)d_in[12];
    const float *Wn2= (const float*)d_in[13], *bn2= (const float*)d_in[14];
    const float *Wb1= (const float*)d_in[15], *bb1= (const float*)d_in[16];
    const float *Wb2= (const float*)d_in[17], *bb2= (const float*)d_in[18];

    const int N = in_sizes[0] / 32;
    const int E = in_sizes[1] / 2;
    const int* rows = ei;       // edge_index[0] = source
    const int* cols = ei + E;   // edge_index[1] = target

    float* out = (float*)d_out;
    float* out_t  = out;              // [256,2]
    float* out_n  = out + NG * 2;     // [N,1]
    float* out_bb = out + NG * 2 + N; // [256,3]

    const int nHist  = (E / 2 + 255) / 256;
    const int nScale = (N * 8 + 255) / 256;
    const int nPlace = (E / 2 + 255) / 256;
    k_g1h<<<GB + nHist, 256>>>(x, W1, cols, E, N);
    k_blocksum<<<NB, 256>>>();
    k_offsets<<<NB, 256>>>(E);
    k_placescale<<<nScale + nPlace, 256>>>(rows, cols, E, N, nScale);
    k_aggrfin1<<<(N + 31) / 32, 128>>>(b1, W2, N);
    k_aggrfin2<<<(N + 63) / 64, 192>>>(b2, Wn1, bn1, Wn2, bn2, bat, N);
    k_nbf<<<(N + 255) / 256, 256>>>(bat, out_n, N);
    k_heads<<<1, NG>>>(Wg, bg, Wt, bt, Wb1, bb1, Wb2, bb2, out_t, out_bb);
}

// round 16
// speedup vs baseline: 1.0453x; 1.0230x over previous
#include <cuda_runtime.h>
#include <cuda_fp16.h>
#include <math.h>

#define NN 100000
#define NE 3200000
#define NG 256
#define NB 391             // ceil(NN/256)
#define GB 391             // gemm1 blocks in fused kernel
#define FULL 0xffffffffu

// -------- scratch --------
__device__ __align__(128) __half g_u1h[NN * 32];   // (x@W1)*dinv, fp16
__device__ __align__(128) __half g_u2h[NN * 24];   // (h1@W2)*dinv, fp16
__device__ __align__(128) __half g_h2h[NN * 24];   // h2, fp16
__device__ __align__(16) float  g_nlog[NN];        // exp(node logit)
__device__ float    g_dinv[NN];
__device__ int      g_cnti[NN];      // self-cleaned in k_offsets
__device__ int      g_off [NN + 1];
__device__ int      g_cur [NN];
__device__ __align__(16) int g_srt [NE];
__device__ int      g_bsum[NB];
__device__ __align__(16) float g_gsum_h2[NG * 24];
__device__ __align__(16) float g_bfeat  [NG * 24];
__device__ float    g_cnt  [NG];
__device__ float    g_gsumn[NG];

// ---------------- helpers ----------------
__device__ __forceinline__ float bfly24(float v) {
#pragma unroll
    for (int d = 16; d >= 1; d >>= 1) v += __shfl_xor_sync(FULL, v, d);
    return v;
}
__device__ __forceinline__ void acc8(float* a, uint4 u) {
    const __half2* hp = (const __half2*)&u;
#pragma unroll
    for (int p = 0; p < 4; p++) {
        float2 f = __half22float2(hp[p]);
        a[p*2+0] += f.x; a[p*2+1] += f.y;
    }
}

// ---------------- kernels ----------------

// in-degree histogram, 2 edges/thread (edge_index is int32 — JAX x64 disabled)
__global__ void k_hist(const int* __restrict__ cols, int E) {
    int e = (blockIdx.x * blockDim.x + threadIdx.x) * 2;
    if (e + 1 < E) {
        int2 c = *(const int2*)(cols + e);
        if ((unsigned)c.x < NN) atomicAdd(&g_cnti[c.x], 1);
        if ((unsigned)c.y < NN) atomicAdd(&g_cnti[c.y], 1);
    } else if (e < E) {
        unsigned c = (unsigned)cols[e];
        if (c < NN) atomicAdd(&g_cnti[c], 1);
    }
}

// per-256-block sums of histogram + dinv; block 0 zeroes per-graph scratch
__global__ __launch_bounds__(256) void k_blocksum() {
    if (blockIdx.x == 0) {
        for (int q = threadIdx.x; q < NG * 24; q += 256) { g_gsum_h2[q] = 0.0f; g_bfeat[q] = 0.0f; }
        if (threadIdx.x < NG) { g_cnt[threadIdx.x] = 0.0f; g_gsumn[threadIdx.x] = 0.0f; }
    }
    __shared__ int s[256];
    int i = blockIdx.x * 256 + threadIdx.x;
    int v = (i < NN) ? g_cnti[i] : 0;
    if (i < NN) g_dinv[i] = rsqrtf((float)(v + 1));
    s[threadIdx.x] = v;
    __syncthreads();
#pragma unroll
    for (int d = 128; d >= 32; d >>= 1) {
        if (threadIdx.x < d) s[threadIdx.x] += s[threadIdx.x + d];
        __syncthreads();
    }
    if (threadIdx.x < 32) {
        int w = s[threadIdx.x];
#pragma unroll
        for (int d = 16; d >= 1; d >>= 1) w += __shfl_xor_sync(FULL, w, d);
        if (threadIdx.x == 0) g_bsum[blockIdx.x] = w;
    }
}

// offsets: each block computes its own prefix over g_bsum, then local exclusive scan;
// also cursors + cnti self-clean
__global__ __launch_bounds__(256) void k_offsets(int E) {
    __shared__ int s[256];
    __shared__ int s_pre;
    int t = threadIdx.x;
    int blk = blockIdx.x;
    int v1 = (t < blk) ? g_bsum[t] : 0;
    if (t + 256 < blk) v1 += g_bsum[t + 256];
    s[t] = v1;
    __syncthreads();
#pragma unroll
    for (int d = 128; d >= 1; d >>= 1) {
        if (t < d) s[t] += s[t + d];
        __syncthreads();
    }
    if (t == 0) s_pre = s[0];
    __syncthreads();
    int i = blk * 256 + t;
    int v = (i < NN) ? g_cnti[i] : 0;
    s[t] = v;
    __syncthreads();
#pragma unroll
    for (int d = 1; d < 256; d <<= 1) {
        int x = (t >= d) ? s[t - d] : 0;
        __syncthreads();
        s[t] += x;
        __syncthreads();
    }
    if (i < NN) {
        int o = s_pre + s[t] - v;
        g_off[i] = o;
        g_cur[i] = o;
        g_cnti[i] = 0;                        // self-clean for graph replay
    }
    if (i == NN - 1) g_off[NN] = E;
}

// FUSED dual-role kernel: blocks [0,GB) do gemm1, blocks [GB,...) do CSR placement
__global__ __launch_bounds__(256) void k_gemm1place(const float* __restrict__ x,
                                                    const float* __restrict__ W1,
                                                    const int* __restrict__ rows,
                                                    const int* __restrict__ cols,
                                                    int E, int n) {
    __shared__ float4 Ws[32 * 8];
    if (blockIdx.x >= GB) {
        int e = ((blockIdx.x - GB) * 256 + threadIdx.x) * 2;
        if (e + 1 < E) {
            int2 r = *(const int2*)(rows + e);
            int2 c = *(const int2*)(cols + e);
            if ((unsigned)c.x < NN && (unsigned)r.x < NN) g_srt[atomicAdd(&g_cur[c.x], 1)] = r.x;
            if ((unsigned)c.y < NN && (unsigned)r.y < NN) g_srt[atomicAdd(&g_cur[c.y], 1)] = r.y;
        } else if (e < E) {
            unsigned c = (unsigned)cols[e], r = (unsigned)rows[e];
            if (c < NN && r < NN) g_srt[atomicAdd(&g_cur[c], 1)] = (int)r;
        }
        return;
    }
    for (int t = threadIdx.x; t < 256; t += 256) Ws[t] = ((const float4*)W1)[t];
    __syncthreads();
    int i = blockIdx.x * 256 + threadIdx.x;
    if (i >= n) return;
    float a[32];
#pragma unroll
    for (int j = 0; j < 32; j++) a[j] = 0.0f;
    const float4* xr = (const float4*)(x + (size_t)i * 32);
#pragma unroll
    for (int k4 = 0; k4 < 8; k4++) {
        float4 xv = xr[k4];
        float xs[4] = {xv.x, xv.y, xv.z, xv.w};
#pragma unroll
        for (int c = 0; c < 4; c++) {
            float v = xs[c];
            int k = k4 * 4 + c;
#pragma unroll
            for (int j4 = 0; j4 < 8; j4++) {
                float4 w = Ws[k * 8 + j4];
                a[j4*4+0] = fmaf(v, w.x, a[j4*4+0]);
                a[j4*4+1] = fmaf(v, w.y, a[j4*4+1]);
                a[j4*4+2] = fmaf(v, w.z, a[j4*4+2]);
                a[j4*4+3] = fmaf(v, w.w, a[j4*4+3]);
            }
        }
    }
    float di = g_dinv[i];
    __half2 hp[16];
#pragma unroll
    for (int p = 0; p < 16; p++) hp[p] = __floats2half2_rn(a[p*2] * di, a[p*2+1] * di);
    uint4* out = (uint4*)g_u1h + (size_t)i * 4;
    const uint4* src = (const uint4*)hp;
#pragma unroll
    for (int q = 0; q < 4; q++) out[q] = src[q];
}

// fused: aggregate conv1 (4 thr/node, fp16 gather, int4 index loads) + relu/bias + GEMM W2
__global__ __launch_bounds__(128) void k_aggrfin1(const float* __restrict__ b1,
                                                  const float* __restrict__ W2, int n) {
    __shared__ float Ws[32 * 24];
    __shared__ float bs[32];
    __shared__ float hs[32][33];
    for (int t = threadIdx.x; t < 768; t += 128) Ws[t] = W2[t];
    if (threadIdx.x < 32) bs[threadIdx.x] = b1[threadIdx.x];
    int local = threadIdx.x >> 2;
    int sub   = threadIdx.x & 3;       // 8 feats each (16B)
    int node  = blockIdx.x * 32 + local;
    bool valid = node < n;
    float acc[8];
#pragma unroll
    for (int f = 0; f < 8; f++) acc[f] = 0.0f;
    float di = 0.0f;
    if (valid) {
        const uint4* U = (const uint4*)g_u1h;
        acc8(acc, U[(size_t)node * 4 + sub]);     // self loop
        int s = g_off[node], e = g_off[node + 1];
        int j = s;
        for (; j < e && (j & 3); j++) acc8(acc, U[(size_t)g_srt[j] * 4 + sub]);
        for (; j + 4 <= e; j += 4) {
            int4 rr = *(const int4*)(g_srt + j);
            uint4 v0 = U[(size_t)rr.x * 4 + sub];
            uint4 v1 = U[(size_t)rr.y * 4 + sub];
            uint4 v2 = U[(size_t)rr.z * 4 + sub];
            uint4 v3 = U[(size_t)rr.w * 4 + sub];
            acc8(acc, v0); acc8(acc, v1); acc8(acc, v2); acc8(acc, v3);
        }
        for (; j < e; j++) acc8(acc, U[(size_t)g_srt[j] * 4 + sub]);
        di = g_dinv[node];
#pragma unroll
        for (int f = 0; f < 8; f++)
            hs[local][sub * 8 + f] = fmaxf(di * acc[f] + bs[sub * 8 + f], 0.0f);
    }
    __syncthreads();
    if (!valid) return;
    float a[6];
#pragma unroll
    for (int q = 0; q < 6; q++) a[q] = 0.0f;
#pragma unroll
    for (int k = 0; k < 32; k++) {
        float v = hs[local][k];
        const float* wr = &Ws[k * 24 + sub * 6];
#pragma unroll
        for (int q = 0; q < 6; q++) a[q] = fmaf(v, wr[q], a[q]);
    }
    __half2* out = (__half2*)(g_u2h + (size_t)node * 24 + sub * 6);
#pragma unroll
    for (int q = 0; q < 3; q++)
        out[q] = __floats2half2_rn(a[q*2] * di, a[q*2+1] * di);
}

// fused: aggregate conv2 (3 thr/node, int4 index loads) + h2 fp16 + node MLP + exp + per-graph sums
__global__ __launch_bounds__(192) void k_aggrfin2(const float* __restrict__ b2,
                                                  const float* __restrict__ Wn1, const float* __restrict__ bn1,
                                                  const float* __restrict__ Wn2, const float* __restrict__ bn2,
                                                  const int* __restrict__ batch, int n) {
    __shared__ float W1s[24 * 16];
    __shared__ float b1s[16];
    __shared__ float W2s[16];
    __shared__ float b2s[24];
    __shared__ float hs[64][25];
    for (int t = threadIdx.x; t < 384; t += 192) W1s[t] = Wn1[t];
    if (threadIdx.x < 16) { b1s[threadIdx.x] = bn1[threadIdx.x]; W2s[threadIdx.x] = Wn2[threadIdx.x]; }
    if (threadIdx.x < 24) b2s[threadIdx.x] = b2[threadIdx.x];
    int local = threadIdx.x / 3;
    int sub   = threadIdx.x % 3;       // 8 feats each (16B)
    int node  = blockIdx.x * 64 + local;
    bool valid = (node < n) && (local < 64);
    float acc[8];
#pragma unroll
    for (int f = 0; f < 8; f++) acc[f] = 0.0f;
    if (valid) {
        const uint4* U = (const uint4*)g_u2h;
        acc8(acc, U[(size_t)node * 3 + sub]);     // self loop
        int s = g_off[node], e = g_off[node + 1];
        int j = s;
        for (; j < e && (j & 3); j++) acc8(acc, U[(size_t)g_srt[j] * 3 + sub]);
        for (; j + 4 <= e; j += 4) {
            int4 rr = *(const int4*)(g_srt + j);
            uint4 v0 = U[(size_t)rr.x * 3 + sub];
            uint4 v1 = U[(size_t)rr.y * 3 + sub];
            uint4 v2 = U[(size_t)rr.z * 3 + sub];
            uint4 v3 = U[(size_t)rr.w * 3 + sub];
            acc8(acc, v0); acc8(acc, v1); acc8(acc, v2); acc8(acc, v3);
        }
        for (; j < e; j++) acc8(acc, U[(size_t)g_srt[j] * 3 + sub]);
        float di = g_dinv[node];
        __half2 hp[4];
#pragma unroll
        for (int p = 0; p < 4; p++) {
            float h0 = fmaxf(di * acc[p*2+0] + b2s[sub*8 + p*2+0], 0.0f);
            float h1 = fmaxf(di * acc[p*2+1] + b2s[sub*8 + p*2+1], 0.0f);
            hs[local][sub*8 + p*2+0] = h0;
            hs[local][sub*8 + p*2+1] = h1;
            hp[p] = __floats2half2_rn(h0, h1);
        }
        ((uint4*)g_h2h)[(size_t)node * 3 + sub] = *(const uint4*)hp;
    }
    __syncthreads();
    // phase 3: warps 0,1 — one node per lane
    if (threadIdx.x >= 64) return;
    int tid = threadIdx.x;
    int node2 = blockIdx.x * 64 + tid;
    bool v2 = node2 < n;
    float h[24];
    float ex = 0.0f;
    unsigned b = 0xffffffffu;
    if (v2) {
#pragma unroll
        for (int k = 0; k < 24; k++) h[k] = hs[tid][k];
        float m[16];
#pragma unroll
        for (int o = 0; o < 16; o++) m[o] = b1s[o];
#pragma unroll
        for (int k = 0; k < 24; k++) {
            float v = h[k];
            const float* wr = &W1s[k * 16];
#pragma unroll
            for (int o = 0; o < 16; o++) m[o] = fmaf(v, wr[o], m[o]);
        }
        float nl = bn2[0];
#pragma unroll
        for (int o = 0; o < 16; o++) nl = fmaf(fmaxf(m[o], 0.0f), W2s[o], nl);
        ex = __expf(nl);
        g_nlog[node2] = ex;
        b = (unsigned)batch[node2];
    } else {
#pragma unroll
        for (int k = 0; k < 24; k++) h[k] = 0.0f;
    }
    unsigned mask = __match_any_sync(FULL, b);
    int lane = tid & 31;
    if (mask == FULL && v2) {
        float se = bfly24(ex);
#pragma unroll
        for (int j = 0; j < 24; j++) {
            float v = bfly24(h[j]);
            if (lane == j) atomicAdd(&g_gsum_h2[b * 24 + j], v);
        }
        if (lane == 24) atomicAdd(&g_cnt[b], 32.0f);
        if (lane == 25) atomicAdd(&g_gsumn[b], se);
    } else if (v2 && b < NG) {
        atomicAdd(&g_cnt[b], 1.0f);
        atomicAdd(&g_gsumn[b], ex);
#pragma unroll
        for (int j = 0; j < 24; j++) atomicAdd(&g_gsum_h2[b * 24 + j], h[j]);
    }
}

// n = e/gsum; write out_n; bfeat[b] += n*h2[i]  (direct coalesced row loads, warp-segmented)
__global__ __launch_bounds__(256) void k_nbf(const int* __restrict__ batch,
                                             float* __restrict__ out_n, int n) {
    int i = blockIdx.x * blockDim.x + threadIdx.x;
    bool valid = i < n;
    unsigned b = 0xffffffffu;
    float val = 0.0f;
    float h[24];
    if (valid) {
        b = (unsigned)batch[i];
        val = g_nlog[i] / g_gsumn[b];
        out_n[i] = val;
        const uint4* hr = (const uint4*)(g_h2h + (size_t)i * 24);
#pragma unroll
        for (int k = 0; k < 3; k++) {
            uint4 u = hr[k];
            const __half2* hp = (const __half2*)&u;
#pragma unroll
            for (int p = 0; p < 4; p++) {
                float2 f = __half22float2(hp[p]);
                h[k*8 + p*2+0] = f.x; h[k*8 + p*2+1] = f.y;
            }
        }
    } else {
#pragma unroll
        for (int j = 0; j < 24; j++) h[j] = 0.0f;
    }
    unsigned mask = __match_any_sync(FULL, b);
    int lane = threadIdx.x & 31;
    if (mask == FULL && valid) {
#pragma unroll
        for (int j = 0; j < 24; j++) {
            float v = bfly24(val * h[j]);
            if (lane == j) atomicAdd(&g_bfeat[b * 24 + j], v);
        }
    } else if (valid && b < NG) {
#pragma unroll
        for (int j = 0; j < 24; j++) atomicAdd(&g_bfeat[b * 24 + j], val * h[j]);
    }
}

// per-graph heads
__global__ __launch_bounds__(256) void k_heads(const float* __restrict__ Wg, const float* __restrict__ bg,
                                               const float* __restrict__ Wt, const float* __restrict__ bt,
                                               const float* __restrict__ Wb1, const float* __restrict__ bb1,
                                               const float* __restrict__ Wb2, const float* __restrict__ bb2,
                                               float* __restrict__ out_t, float* __restrict__ out_bb) {
    __shared__ float sBB[NG * 3];
    __shared__ float cmax[3], csum[3];
    int b = threadIdx.x;

    float c = fmaxf(g_cnt[b], 1.0f);
    float g24[24];
#pragma unroll
    for (int j = 0; j < 24; j++) g24[j] = g_gsum_h2[b * 24 + j] / c;
    float t0 = bt[0], t1 = bt[1];
    for (int o = 0; o < 32; o++) {
        float go = bg[o];
#pragma unroll
        for (int k = 0; k < 24; k++) go = fmaf(g24[k], Wg[k * 32 + o], go);
        t0 = fmaf(go, Wt[o * 2 + 0], t0);
        t1 = fmaf(go, Wt[o * 2 + 1], t1);
    }
    float mx = fmaxf(t0, t1);
    float e0 = __expf(t0 - mx), e1 = __expf(t1 - mx);
    float s = e0 + e1;
    out_t[2 * b + 0] = e0 / s;
    out_t[2 * b + 1] = e1 / s;

    float bf[24];
#pragma unroll
    for (int k = 0; k < 24; k++) bf[k] = g_bfeat[b * 24 + k];
    float r16[16];
#pragma unroll
    for (int o = 0; o < 16; o++) {
        float v = bb1[o];
#pragma unroll
        for (int k = 0; k < 24; k++) v = fmaf(bf[k], Wb1[k * 16 + o], v);
        r16[o] = fmaxf(v, 0.0f);
    }
#pragma unroll
    for (int o = 0; o < 3; o++) {
        float v = bb2[o];
#pragma unroll
        for (int k = 0; k < 16; k++) v = fmaf(r16[k], Wb2[k * 3 + o], v);
        sBB[b * 3 + o] = v;
    }
    __syncthreads();
    if (b < 3) {
        float m = -3.4e38f;
        for (int r = 0; r < NG; r++) m = fmaxf(m, sBB[r * 3 + b]);
        float ss = 0.0f;
        for (int r = 0; r < NG; r++) ss += __expf(sBB[r * 3 + b] - m);
        cmax[b] = m; csum[b] = ss;
    }
    __syncthreads();
#pragma unroll
    for (int o = 0; o < 3; o++)
        out_bb[b * 3 + o] = __expf(sBB[b * 3 + o] - cmax[o]) / csum[o];
}

// ---------------- launcher ----------------
extern "C" void kernel_launch(void* const* d_in, const int* in_sizes, int n_in,
                              void* d_out, int out_size) {
    const float* x   = (const float*)d_in[0];
    const int*   ei  = (const int*)d_in[1];
    const int*   bat = (const int*)d_in[2];
    const float *W1 = (const float*)d_in[3],  *b1 = (const float*)d_in[4];
    const float *W2 = (const float*)d_in[5];
    const float *b2 = (const float*)d_in[6];
    const float *Wg = (const float*)d_in[7],  *bg = (const float*)d_in[8];
    const float *Wt = (const float*)d_in[9],  *bt = (const float*)d_in[10];
    const float *Wn1= (const float*)d_in[11], *bn1= (const float*)d_in[12];
    const float *Wn2= (const float*)d_in[13], *bn2= (const float*)d_in[14];
    const float *Wb1= (const float*)d_in[15], *bb1= (const float*)d_in[16];
    const float *Wb2= (const float*)d_in[17], *bb2= (const float*)d_in[18];

    const int N = in_sizes[0] / 32;
    const int E = in_sizes[1] / 2;
    const int* rows = ei;       // edge_index[0] = source
    const int* cols = ei + E;   // edge_index[1] = target

    float* out = (float*)d_out;
    float* out_t  = out;              // [256,2]
    float* out_n  = out + NG * 2;     // [N,1]
    float* out_bb = out + NG * 2 + N; // [256,3]

    const int TB = 256;
    const int nPlace = (E / 2 + 255) / 256;
    k_hist<<<(E / 2 + TB - 1) / TB, TB>>>(cols, E);
    k_blocksum<<<NB, 256>>>();
    k_offsets<<<NB, 256>>>(E);
    k_gemm1place<<<GB + nPlace, 256>>>(x, W1, rows, cols, E, N);
    k_aggrfin1<<<(N + 31) / 32, 128>>>(b1, W2, N);
    k_aggrfin2<<<(N + 63) / 64, 192>>>(b2, Wn1, bn1, Wn2, bn2, bat, N);
    k_nbf<<<(N + 255) / 256, 256>>>(bat, out_n, N);
    k_heads<<<1, NG>>>(Wg, bg, Wt, bt, Wb1, bb1, Wb2, bb2, out_t, out_bb);
}